// round 17
// baseline (speedup 1.0000x reference)
#include <cuda_runtime.h>
#include <cuda_bf16.h>
#include <cstdint>

#define BATCH   32768
#define NSITES  64
#define NPAIR   31
#define NSETS   (NPAIR * 4)            // 124 pass-sets
#define TPB     32
#define NCTA    (BATCH / 32)           // 1024 single-warp CTAs, 2 chains x 16 samples

// Fragment-linear bf16 hi/lo B operands for fused site-pairs:
// set S = pair*4 + g,  g: 0=M0aM0b, 1=DaM0b, 2=M0aDb, 3=DaDb
// word index = (((S*2 + limb)*4 + j)*32 + lane)*4 + m   (limb 0=hi, 1=lo)
__device__ __align__(256) uint4 g_bfrags[(NSETS + 1) * 2 * 4 * 32];

// ---------------- helpers ----------------
__device__ __forceinline__ void mma16816(float* d, const uint32_t* a, uint32_t b0, uint32_t b1) {
    asm("mma.sync.aligned.m16n8k16.row.col.f32.bf16.bf16.f32 "
        "{%0,%1,%2,%3}, {%4,%5,%6,%7}, {%8,%9}, {%0,%1,%2,%3};"
        : "+f"(d[0]), "+f"(d[1]), "+f"(d[2]), "+f"(d[3])
        : "r"(a[0]), "r"(a[1]), "r"(a[2]), "r"(a[3]), "r"(b0), "r"(b1));
}
__device__ __forceinline__ void mma16816_z(float* d, const uint32_t* a, uint32_t b0, uint32_t b1,
                                           const float* z) {
    asm("mma.sync.aligned.m16n8k16.row.col.f32.bf16.bf16.f32 "
        "{%0,%1,%2,%3}, {%4,%5,%6,%7}, {%8,%9}, {%10,%11,%12,%13};"
        : "=f"(d[0]), "=f"(d[1]), "=f"(d[2]), "=f"(d[3])
        : "r"(a[0]), "r"(a[1]), "r"(a[2]), "r"(a[3]), "r"(b0), "r"(b1),
          "f"(z[0]), "f"(z[1]), "f"(z[2]), "f"(z[3]));
}
__device__ __forceinline__ uint32_t packbf(float lo, float hi) {
    uint32_t r;
    asm("cvt.rn.bf16x2.f32 %0, %1, %2;" : "=r"(r) : "f"(hi), "f"(lo));
    return r;
}
__device__ __forceinline__ uint32_t packbf_trunc(uint32_t u0, uint32_t u1) {
    uint32_t r;
    asm("prmt.b32 %0, %1, %2, 0x7632;" : "=r"(r) : "r"(u0), "r"(u1));
    return r;
}
__device__ __forceinline__ void split2(float x0, float x1, uint32_t& hp, uint32_t& lp) {
    uint32_t u0 = __float_as_uint(x0), u1 = __float_as_uint(x1);
    hp = packbf_trunc(u0, u1);
    float l0 = x0 - __uint_as_float(u0 & 0xFFFF0000u);
    float l1 = x1 - __uint_as_float(u1 & 0xFFFF0000u);
    lp = packbf(l0, l1);
}

// one 24-MMA pass (M=16), term-major
__device__ __forceinline__ void do_pass(float acc[4][4],
                                        const uint32_t ah[2][4],
                                        const uint32_t al[2][4],
                                        const uint4* b) {
    #pragma unroll
    for (int j = 0; j < 4; j++) mma16816(acc[j], ah[0], b[j].x, b[j].y);
    #pragma unroll
    for (int j = 0; j < 4; j++) mma16816(acc[j], ah[1], b[j].z, b[j].w);
    #pragma unroll
    for (int j = 0; j < 4; j++) mma16816(acc[j], al[0], b[j].x, b[j].y);
    #pragma unroll
    for (int j = 0; j < 4; j++) mma16816(acc[j], al[1], b[j].z, b[j].w);
    #pragma unroll
    for (int j = 0; j < 4; j++) mma16816(acc[j], ah[0], b[4+j].x, b[4+j].y);
    #pragma unroll
    for (int j = 0; j < 4; j++) mma16816(acc[j], ah[1], b[4+j].z, b[4+j].w);
}
__device__ __forceinline__ void do_pass_first(float acc[4][4],
                                              const uint32_t ah[2][4],
                                              const uint32_t al[2][4],
                                              const uint4* b, const float* z4) {
    #pragma unroll
    for (int j = 0; j < 4; j++) mma16816_z(acc[j], ah[0], b[j].x, b[j].y, z4);
    #pragma unroll
    for (int j = 0; j < 4; j++) mma16816(acc[j], ah[1], b[j].z, b[j].w);
    #pragma unroll
    for (int j = 0; j < 4; j++) mma16816(acc[j], al[0], b[j].x, b[j].y);
    #pragma unroll
    for (int j = 0; j < 4; j++) mma16816(acc[j], al[1], b[j].z, b[j].w);
    #pragma unroll
    for (int j = 0; j < 4; j++) mma16816(acc[j], ah[0], b[4+j].x, b[4+j].y);
    #pragma unroll
    for (int j = 0; j < 4; j++) mma16816(acc[j], ah[1], b[4+j].z, b[4+j].w);
}

__device__ __forceinline__ void mask_copy(uint32_t dh[2][4], uint32_t dl[2][4],
                                          const uint32_t sh[2][4], const uint32_t sl[2][4],
                                          uint32_t c0, uint32_t c1) {
    #pragma unroll
    for (int kt = 0; kt < 2; kt++)
        #pragma unroll
        for (int h = 0; h < 2; h++) {
            dh[kt][2*h]   = c0 ? sh[kt][2*h]   : 0u;
            dl[kt][2*h]   = c0 ? sl[kt][2*h]   : 0u;
            dh[kt][2*h+1] = c1 ? sh[kt][2*h+1] : 0u;
            dl[kt][2*h+1] = c1 ? sl[kt][2*h+1] : 0u;
        }
}

// select+pass for one g-set of one chain (g is compile-time)
__device__ __forceinline__ void do_g(int g, float acc[4][4],
                                     uint32_t ah[2][4], uint32_t al[2][4],
                                     uint32_t th[2][4], uint32_t tl[2][4],
                                     uint32_t c1x, uint32_t c1y,
                                     uint32_t c2x, uint32_t c2y,
                                     const uint4* cur, const float* z4) {
    if (g == 0) {
        do_pass_first(acc, ah, al, cur, z4);
    } else if (g == 1) {
        mask_copy(th, tl, ah, al, c1x, c1y);
        do_pass(acc, th, tl, cur);
    } else if (g == 2) {
        mask_copy(th, tl, ah, al, c2x, c2y);
        do_pass(acc, th, tl, cur);
    } else {
        #pragma unroll
        for (int kt = 0; kt < 2; kt++)
            #pragma unroll
            for (int h = 0; h < 2; h++) {
                th[kt][2*h]   = c1x ? th[kt][2*h]   : 0u;
                tl[kt][2*h]   = c1x ? tl[kt][2*h]   : 0u;
                th[kt][2*h+1] = c1y ? th[kt][2*h+1] : 0u;
                tl[kt][2*h+1] = c1y ? tl[kt][2*h+1] : 0u;
            }
        do_pass(acc, th, tl, cur);
    }
}

__device__ __forceinline__ void split_env(const float acc[4][4],
                                          uint32_t ah[2][4], uint32_t al[2][4]) {
    #pragma unroll
    for (int kt = 0; kt < 2; kt++)
        #pragma unroll
        for (int h = 0; h < 2; h++) {
            uint32_t hA, lA, hB, lB;
            split2(acc[2 * kt + h][0], acc[2 * kt + h][1], hA, lA);
            split2(acc[2 * kt + h][2], acc[2 * kt + h][3], hB, lB);
            ah[kt][2 * h]     = hA;  ah[kt][2 * h + 1] = hB;
            al[kt][2 * h]     = lA;  al[kt][2 * h + 1] = lB;
        }
}

// ---------------- prep: one block per (pair,g) pass-set; SMEM-staged tiny GEMM ----------------
__global__ void prep_kernel(const float* __restrict__ bulk) {
    const int S = blockIdx.x;                        // 0..123
    const int p = S >> 2;
    const int g = S & 3;
    const int selA = g & 1, selB = g >> 1;
    const float* ba = bulk + (size_t)(2 * p)     * 2048;
    const float* bb = bulk + (size_t)(2 * p + 1) * 2048;

    __shared__ float Ma[1024];
    __shared__ float Mb[1024];
    __shared__ float G[1024];

    for (int i = threadIdx.x; i < 1024; i += blockDim.x) {
        int r = i >> 5, c = i & 31;
        float va = ba[(r * 2 + 0) * 32 + c];
        if (selA) va = ba[(r * 2 + 1) * 32 + c] - va;
        Ma[i] = va;
        float vb = bb[(r * 2 + 0) * 32 + c];
        if (selB) vb = bb[(r * 2 + 1) * 32 + c] - vb;
        Mb[i] = vb;
    }
    __syncthreads();

    for (int i = threadIdx.x; i < 1024; i += blockDim.x) {
        int d = i >> 5, e = i & 31;
        float s = 0.0f;
        #pragma unroll
        for (int m = 0; m < 32; m++) s += Ma[d * 32 + m] * Mb[m * 32 + e];
        G[i] = s;
    }
    __syncthreads();

    for (int idx = threadIdx.x; idx < 2048; idx += blockDim.x) {
        int m    = idx & 3;
        int lane = (idx >> 2) & 31;
        int j    = (idx >> 7) & 3;
        int limb = (idx >> 9) & 1;
        int n = 8 * j + (lane >> 2);
        int k = 8 * m + 2 * (lane & 3);
        float x0 = G[k * 32 + n];
        float x1 = G[(k + 1) * 32 + n];
        float v0, v1;
        if (limb) {
            __nv_bfloat16 h0 = __float2bfloat16(x0);
            __nv_bfloat16 h1 = __float2bfloat16(x1);
            v0 = x0 - __bfloat162float(h0);
            v1 = x1 - __bfloat162float(h1);
        } else { v0 = x0; v1 = x1; }
        ((uint32_t*)g_bfrags)[(((S * 2 + limb) * 4 + j) * 32 + lane) * 4 + m] = packbf(v0, v1);
    }
}

// ---------------- main kernel: TWO M=16 chains per warp, software-pipelined ----------------
__global__ void __launch_bounds__(TPB)
mps_mma_kernel(const int*   __restrict__ conf,
               const float* __restrict__ left,
               const float* __restrict__ right,
               float*       __restrict__ out)
{
    __shared__ float lt_s[64];
    __shared__ float rt_s[64];
    __shared__ unsigned long long masks_s[32];

    const int lane = threadIdx.x;
    const int rowq = lane >> 2;
    const int q    = lane & 3;

    lt_s[lane] = left[lane];   lt_s[lane + 32] = left[lane + 32];
    rt_s[lane] = right[lane];  rt_s[lane + 32] = right[lane + 32];

    {
        unsigned long long mask = 0;
        const int4* cp4 = (const int4*)(conf + (size_t)(blockIdx.x * 32 + lane) * NSITES);
        #pragma unroll
        for (int i = 0; i < NSITES / 4; i++) {
            int4 v = cp4[i];
            mask |= ((unsigned long long)(v.x & 1) << (4 * i))
                  | ((unsigned long long)(v.y & 1) << (4 * i + 1))
                  | ((unsigned long long)(v.z & 1) << (4 * i + 2))
                  | ((unsigned long long)(v.w & 1) << (4 * i + 3));
        }
        masks_s[lane] = mask;
    }
    __syncwarp();

    // chain A: samples 0..15; chain B: samples 16..31
    const unsigned long long mrA0 = masks_s[rowq];
    const unsigned long long mrA1 = masks_s[rowq + 8];
    const unsigned long long mrB0 = masks_s[16 + rowq];
    const unsigned long long mrB1 = masks_s[16 + rowq + 8];

    uint32_t ahA[2][4], alA[2][4], ahB[2][4], alB[2][4];
    {
        const int cA0 = (int)(mrA0 & 1ull), cA1 = (int)(mrA1 & 1ull);
        const int cB0 = (int)(mrB0 & 1ull), cB1 = (int)(mrB1 & 1ull);
        #pragma unroll
        for (int kt = 0; kt < 2; kt++)
            #pragma unroll
            for (int h = 0; h < 2; h++) {
                int k0 = 16 * kt + 8 * h + 2 * q;
                uint32_t hx, lx, hy, ly;
                split2(lt_s[cA0 * 32 + k0], lt_s[cA0 * 32 + k0 + 1], hx, lx);
                split2(lt_s[cA1 * 32 + k0], lt_s[cA1 * 32 + k0 + 1], hy, ly);
                ahA[kt][2*h] = hx;  ahA[kt][2*h+1] = hy;
                alA[kt][2*h] = lx;  alA[kt][2*h+1] = ly;
                split2(lt_s[cB0 * 32 + k0], lt_s[cB0 * 32 + k0 + 1], hx, lx);
                split2(lt_s[cB1 * 32 + k0], lt_s[cB1 * 32 + k0 + 1], hy, ly);
                ahB[kt][2*h] = hx;  ahB[kt][2*h+1] = hy;
                alB[kt][2*h] = lx;  alB[kt][2*h+1] = ly;
            }
    }

    const uint4* fb = g_bfrags + lane;

    // two shared fragment buffers; prologue: set 0 -> X
    uint4 X[8], Y[8];
    #pragma unroll
    for (int j = 0; j < 4; j++) {
        X[j]     = __ldg(fb + ((0 * 2 + 0) * 4 + j) * 32);
        X[4 + j] = __ldg(fb + ((0 * 2 + 1) * 4 + j) * 32);
    }

    const float z4[4] = {0.0f, 0.0f, 0.0f, 0.0f};
    float accA[4][4], accB[4][4];
    uint32_t th[2][4], tl[2][4];

    for (int p = 0; p < NPAIR; p++) {
        const uint32_t cA1a = (uint32_t)((mrA0 >> (2*p+1)) & 1ull);
        const uint32_t cA1b = (uint32_t)((mrA1 >> (2*p+1)) & 1ull);
        const uint32_t cA2a = (uint32_t)((mrA0 >> (2*p+2)) & 1ull);
        const uint32_t cA2b = (uint32_t)((mrA1 >> (2*p+2)) & 1ull);
        const uint32_t cB1a = (uint32_t)((mrB0 >> (2*p+1)) & 1ull);
        const uint32_t cB1b = (uint32_t)((mrB1 >> (2*p+1)) & 1ull);
        const uint32_t cB2a = (uint32_t)((mrB0 >> (2*p+2)) & 1ull);
        const uint32_t cB2b = (uint32_t)((mrB1 >> (2*p+2)) & 1ull);

        // 8 pass slots: sets [0,1,2,3, 0,1,2,3]+4p ; chains [A,A,A,A, B,B,B,B]
        #pragma unroll
        for (int slot = 0; slot < 8; slot++) {
            const int g = slot & 3;
            uint4* cur = (slot & 1) ? Y : X;
            uint4* nxt = (slot & 1) ? X : Y;
            // prefetch next slot's set
            int nS;
            if (slot < 3)       nS = p * 4 + g + 1;
            else if (slot == 3) nS = p * 4;                 // B reuses set 0
            else if (slot < 7)  nS = p * 4 + g + 1;
            else                nS = (p + 1 < NPAIR) ? (p + 1) * 4 : -1;
            if (nS >= 0) {
                #pragma unroll
                for (int j = 0; j < 4; j++) {
                    nxt[j]     = __ldg(fb + ((nS * 2 + 0) * 4 + j) * 32);
                    nxt[4 + j] = __ldg(fb + ((nS * 2 + 1) * 4 + j) * 32);
                }
            }
            if (slot < 4)
                do_g(g, accA, ahA, alA, th, tl, cA1a, cA1b, cA2a, cA2b, cur, z4);
            else
                do_g(g, accB, ahB, alB, th, tl, cB1a, cB1b, cB2a, cB2b, cur, z4);
            // splitA placed between A-passes and B-passes so its ALU chain
            // can be scheduled into B's HMMA stream
            if (slot == 3 && p + 1 < NPAIR) split_env(accA, ahA, alA);
        }
        // splitB at end; overlaps next pair's A passes via scheduler lookahead
        if (p + 1 < NPAIR) split_env(accB, ahB, alB);
    }

    // ---- final dots with right[:, c63]; reduce across the 4 lanes of each row group ----
    {
        const int cA = (int)(mrA0 >> 63), cB = (int)(mrA1 >> 63);
        const int dA = (int)(mrB0 >> 63), dB = (int)(mrB1 >> 63);
        float pa = 0.0f, pb = 0.0f, pc = 0.0f, pd = 0.0f;
        #pragma unroll
        for (int j = 0; j < 4; j++) {
            int n0 = 8 * j + 2 * q;
            pa += accA[j][0] * rt_s[n0 * 2 + cA] + accA[j][1] * rt_s[(n0 + 1) * 2 + cA];
            pb += accA[j][2] * rt_s[n0 * 2 + cB] + accA[j][3] * rt_s[(n0 + 1) * 2 + cB];
            pc += accB[j][0] * rt_s[n0 * 2 + dA] + accB[j][1] * rt_s[(n0 + 1) * 2 + dA];
            pd += accB[j][2] * rt_s[n0 * 2 + dB] + accB[j][3] * rt_s[(n0 + 1) * 2 + dB];
        }
        pa += __shfl_xor_sync(0xFFFFFFFF, pa, 1);
        pa += __shfl_xor_sync(0xFFFFFFFF, pa, 2);
        pb += __shfl_xor_sync(0xFFFFFFFF, pb, 1);
        pb += __shfl_xor_sync(0xFFFFFFFF, pb, 2);
        pc += __shfl_xor_sync(0xFFFFFFFF, pc, 1);
        pc += __shfl_xor_sync(0xFFFFFFFF, pc, 2);
        pd += __shfl_xor_sync(0xFFFFFFFF, pd, 1);
        pd += __shfl_xor_sync(0xFFFFFFFF, pd, 2);
        if (q == 0) {
            int base = blockIdx.x * 32 + rowq;
            out[base]      = pa;
            out[base + 8]  = pb;
            out[base + 16] = pc;
            out[base + 24] = pd;
        }
    }
}

extern "C" void kernel_launch(void* const* d_in, const int* in_sizes, int n_in,
                              void* d_out, int out_size) {
    const int*   conf  = (const int*)d_in[0];
    const float* left  = (const float*)d_in[1];
    const float* bulk  = (const float*)d_in[2];
    const float* right = (const float*)d_in[3];
    float*       out   = (float*)d_out;

    prep_kernel<<<NSETS, 256>>>(bulk);
    mps_mma_kernel<<<NCTA, TPB>>>(conf, left, right, out);
}